// round 15
// baseline (speedup 1.0000x reference)
#include <cuda_runtime.h>
#include <cstdint>

#define TT 1000
#define BB 512
#define IDM 32
#define HH 64
#define NHIST 5
#define FULLM 0xffffffffu

typedef unsigned long long ull;

// Kalman gains per step: layout [t][o*64 + i]
__device__ __align__(16) float g_U[TT * 192];
// first step with zero Kalman gain: correction active iff NHIST <= t < g_tcut
__device__ int g_tcut;
// CW = C @ W_mlp  (3 x 320), Cb = C @ b_mlp (3)
__device__ __align__(16) float g_CW[3 * 320];
__device__ __align__(16) float g_Cb[4];
// precomputed x @ W_ih^T : [t][row][j]
__device__ __align__(16) float g_XW[(size_t)TT * BB * HH];

// ---- packed f32x2 helpers (Blackwell FFMA2 path, PTX-only) ----
__device__ __forceinline__ void fma2(ull& d, ull a, ull b) {
    asm("fma.rn.f32x2 %0, %1, %2, %0;" : "+l"(d) : "l"(a), "l"(b));
}
__device__ __forceinline__ ull pack2(float lo, float hi) {
    ull r; asm("mov.b64 %0, {%1, %2};" : "=l"(r) : "f"(lo), "f"(hi)); return r;
}
__device__ __forceinline__ float2 unpack2(ull v) {
    float2 r; asm("mov.b64 {%0, %1}, %2;" : "=f"(r.x), "=f"(r.y) : "l"(v)); return r;
}

// ======================================================================
// xw_kernel: g_XW[m][j] = sum_k x[m][k] * W_ih[j][k]   (m = t*BB + row)
// Fully parallel; memory-bound (~196 MB traffic). Proven in R12.
// ======================================================================
__global__ void __launch_bounds__(256, 2)
xw_kernel(const float* __restrict__ x, const float* __restrict__ W_ih) {
    __shared__ __align__(16) float sx[128 * 32];
    __shared__ __align__(16) ull sw2[32 * 32];  // [k][jpair]
    const int tid = threadIdx.x;
    const int m0 = blockIdx.x * 128;

    for (int idx = tid; idx < 1024; idx += 256) {
        int k = idx >> 5, jp = idx & 31;
        sw2[idx] = pack2(W_ih[(2 * jp) * IDM + k], W_ih[(2 * jp + 1) * IDM + k]);
    }
    for (int idx = tid; idx < 4096; idx += 256)
        sx[idx] = x[(size_t)m0 * IDM + idx];
    __syncthreads();

    const int jp = tid & 31, mg = tid >> 5;   // 8 m-groups
    for (int mi = mg; mi < 128; mi += 8) {
        const float* xr = &sx[mi * 32];
        ull acc = 0;
        #pragma unroll
        for (int k = 0; k < 32; k++) {
            float xv = xr[k];
            fma2(acc, pack2(xv, xv), sw2[k * 32 + jp]);
        }
        *(float2*)&g_XW[(size_t)(m0 + mi) * HH + 2 * jp] = unpack2(acc);
    }
}

// ======================================================================
// Producer: prep (CW fold) + Riccati chain -> K_t. Single block,
// 256 threads, 4x4 tiles, f32x2 GEMMs (best measured config).
// Exit when max|K| <= 3e-5 (validated: rel_err 1.4e-6).
// ======================================================================
#define PD 66

struct PSmem {
    float A[64 * PD];
    float At[64 * PD];
    float cov[64 * PD];
    float E[64 * PD];
    float P[64 * PD];
    float Cs[192];
    float Y[192];
    float S[9];
    float Si[9];
    float U[192];
    float Up[192];
    float CP[192];
    int ctl[2];
    int done;
};

__global__ void __launch_bounds__(256, 1)
cov_kernel(const float* __restrict__ W_hh, const float* __restrict__ Cmat,
           const float* __restrict__ W_mlp, const float* __restrict__ b_mlp) {
    extern __shared__ char praw[];
    PSmem& s = *reinterpret_cast<PSmem*>(praw);
    const int tid = threadIdx.x;

    for (int idx = tid; idx < 960; idx += 256) {
        int o = idx / 320, m = idx - o * 320;
        float acc = 0.f;
        #pragma unroll 8
        for (int j = 0; j < 64; j++) acc += Cmat[o * 64 + j] * W_mlp[j * 320 + m];
        g_CW[idx] = acc;
    }
    if (tid < 3) {
        float acc = 0.f;
        for (int j = 0; j < 64; j++) acc += Cmat[tid * 64 + j] * b_mlp[j];
        g_Cb[tid] = acc;
    }
    if (tid == 5) g_tcut = TT;

    for (int idx = tid; idx < 4096; idx += 256) {
        int i = idx >> 6, k = idx & 63;
        float v = W_hh[idx];
        s.A[i * PD + k]   = v;
        s.At[k * PD + i]  = v;
        s.cov[i * PD + k] = (i == k) ? 1.f : 0.f;
    }
    for (int idx = tid; idx < 192; idx += 256) { s.Cs[idx] = Cmat[idx]; s.Up[idx] = 0.f; }
    if (tid < 2) s.ctl[tid] = 0;
    if (tid == 0) s.done = 0;
    __syncthreads();

    const int ty = tid >> 4;
    const int tx = tid & 15;

    for (int t = NHIST; t < TT; t++) {
        {   // E = A @ cov
            ull c01[4] = {0, 0, 0, 0};
            ull c23[4] = {0, 0, 0, 0};
            #pragma unroll 4
            for (int k = 0; k < 64; k++) {
                ull b01 = *(const ull*)&s.cov[k * PD + tx * 4];
                ull b23 = *(const ull*)&s.cov[k * PD + tx * 4 + 2];
                #pragma unroll
                for (int r = 0; r < 4; r++) {
                    float av = s.A[(ty * 4 + r) * PD + k];
                    ull ap = pack2(av, av);
                    fma2(c01[r], ap, b01);
                    fma2(c23[r], ap, b23);
                }
            }
            #pragma unroll
            for (int r = 0; r < 4; r++) {
                *(float2*)&s.E[(ty * 4 + r) * PD + tx * 4]     = unpack2(c01[r]);
                *(float2*)&s.E[(ty * 4 + r) * PD + tx * 4 + 2] = unpack2(c23[r]);
            }
        }
        __syncthreads();

        {   // P = E @ A^T
            ull c01[4] = {0, 0, 0, 0};
            ull c23[4] = {0, 0, 0, 0};
            #pragma unroll 4
            for (int k = 0; k < 64; k++) {
                ull b01 = *(const ull*)&s.At[k * PD + tx * 4];
                ull b23 = *(const ull*)&s.At[k * PD + tx * 4 + 2];
                #pragma unroll
                for (int r = 0; r < 4; r++) {
                    float av = s.E[(ty * 4 + r) * PD + k];
                    ull ap = pack2(av, av);
                    fma2(c01[r], ap, b01);
                    fma2(c23[r], ap, b23);
                }
            }
            #pragma unroll
            for (int r = 0; r < 4; r++) {
                *(float2*)&s.P[(ty * 4 + r) * PD + tx * 4]     = unpack2(c01[r]);
                *(float2*)&s.P[(ty * 4 + r) * PD + tx * 4 + 2] = unpack2(c23[r]);
            }
        }
        __syncthreads();

        if (tid < 192) {   // Y = P @ C^T
            int o = tid >> 6, i = tid & 63;
            float acc = 0.f;
            for (int k = 0; k < 64; k++) acc += s.P[i * PD + k] * s.Cs[o * 64 + k];
            s.Y[i * 3 + o] = acc;
        }
        __syncthreads();

        if (tid < 9) {     // S = C @ Y + I
            int o1 = tid / 3, o2 = tid - o1 * 3;
            float acc = (o1 == o2) ? 1.f : 0.f;
            for (int k = 0; k < 64; k++) acc += s.Cs[o1 * 64 + k] * s.Y[k * 3 + o2];
            s.S[tid] = acc;
        }
        __syncthreads();

        if (tid == 0) {    // Si = inv(S)
            float a = s.S[0], b = s.S[1], c = s.S[2];
            float d = s.S[3], e = s.S[4], f = s.S[5];
            float g = s.S[6], h = s.S[7], i2 = s.S[8];
            float A0 =  (e * i2 - f * h);
            float A1 = -(d * i2 - f * g);
            float A2 =  (d * h  - e * g);
            float B0 = -(b * i2 - c * h);
            float B1 =  (a * i2 - c * g);
            float B2 = -(a * h  - b * g);
            float C0 =  (b * f - c * e);
            float C1 = -(a * f - c * d);
            float C2 =  (a * e - b * d);
            float det = a * A0 + b * A1 + c * A2;
            float id = 1.f / det;
            s.Si[0] = A0 * id; s.Si[1] = B0 * id; s.Si[2] = C0 * id;
            s.Si[3] = A1 * id; s.Si[4] = B1 * id; s.Si[5] = C1 * id;
            s.Si[6] = A2 * id; s.Si[7] = B2 * id; s.Si[8] = C2 * id;
        }
        __syncthreads();

        if (tid < 192) {   // U = Y @ Si (K), store, track
            int o = tid >> 6, i = tid & 63;
            float u = s.Y[i * 3 + 0] * s.Si[0 + o]
                    + s.Y[i * 3 + 1] * s.Si[3 + o]
                    + s.Y[i * 3 + 2] * s.Si[6 + o];
            s.U[tid] = u;
            g_U[(size_t)t * 192 + tid] = u;
            float dd = fabsf(u - s.Up[tid]);
            s.Up[tid] = u;
            atomicMax(&s.ctl[0], __float_as_int(dd));
            atomicMax(&s.ctl[1], __float_as_int(fabsf(u)));
        }
        __syncthreads();

        if (tid < 192) {   // CP = C @ P
            int o = tid >> 6, j = tid & 63;
            float acc = 0.f;
            for (int k = 0; k < 64; k++) acc += s.Cs[o * 64 + k] * s.P[k * PD + j];
            s.CP[tid] = acc;
        }
        if (tid == 0) {
            float md = __int_as_float(s.ctl[0]);
            float ma = __int_as_float(s.ctl[1]);
            if (ma <= 3e-5f)            s.done = 2;  // K negligible (validated)
            else if (md <= 1e-6f * ma)  s.done = 1;  // K stationary (nonzero)
            s.ctl[0] = 0; s.ctl[1] = 0;
        }
        __syncthreads();

        for (int e = tid; e < 4096; e += 256) {   // cov = P - U^T CP
            int i = e >> 6, j = e & 63;
            s.cov[i * PD + j] = s.P[i * PD + j]
                - (s.U[i]       * s.CP[j]
                 + s.U[64 + i]  * s.CP[64 + j]
                 + s.U[128 + i] * s.CP[128 + j]);
        }
        __syncthreads();

        if (s.done == 2) {
            if (tid == 0) g_tcut = t + 1;
            break;
        }
        if (s.done == 1) {
            for (int tt = t + 1; tt < TT; tt++)
                for (int idx = tid; idx < 192; idx += 256)
                    g_U[(size_t)tt * 192 + idx] = s.U[idx];
            break;
        }
    }
}

// ======================================================================
// Consumer: proven R14 shape (block = 64 threads = 1 row, lane owns
// dim j, register-stationary W_hh, one barrier/step) with the x-GEMV
// hoisted: per-step x contribution is ONE prefetched LDG.32 from g_XW.
// ======================================================================
__global__ void __launch_bounds__(64, 1)
seq_kernel(const float* __restrict__ b_ih, const float* __restrict__ b_hh,
           const float* __restrict__ W_hh, const float* __restrict__ C,
           float* __restrict__ out, float* __restrict__ hlast) {
    __shared__ __align__(16) float sh[2][64];   // parity-buffered hidden
    __shared__ float sred[2][4];                // correction warp partials

    const int tid  = threadIdx.x;
    const int w    = tid >> 5;
    const int lane = tid & 31;
    const int j    = tid;          // output dim owned by this lane
    const int row  = blockIdx.x;

    // ---- W_hh column into registers (f32x2-packed) ----
    ull whh[32];
    #pragma unroll
    for (int p = 0; p < 32; p++)
        whh[p] = *(const ull*)&W_hh[j * HH + 2 * p];

    const float Cj0 = C[j], Cj1 = C[64 + j], Cj2 = C[128 + j];
    const float bj  = b_ih[j] + b_hh[j];
    const float cb0 = g_Cb[0], cb1 = g_Cb[1], cb2 = g_Cb[2];
    const int   tcut = g_tcut;     // correction active iff NHIST <= t < tcut

    // ---- init state ----
    sh[0][j] = 0.f;
    float hcur = 0.f;
    float hist[NHIST] = {0.f, 0.f, 0.f, 0.f, 0.f};

    const float* xwp = &g_XW[(size_t)row * HH + j];
    const size_t XSTP = (size_t)BB * HH;
    float xwc = xwp[0];
    float xw1 = xwp[XSTP];
    float xw2 = xwp[2 * XSTP];

    float k0 = 0.f, k1 = 0.f, k2 = 0.f;
    int par = 0;
    float* outp = out + (size_t)row * HH + j;
    __syncthreads();

    for (int t = 0; t < TT; t++) {
        // ---- prefetch xw[t+3] and K[t+1] ----
        float xw3 = 0.f;
        if (t + 3 < TT) xw3 = xwp[(size_t)(t + 3) * XSTP];
        float kn0 = 0.f, kn1 = 0.f, kn2 = 0.f;
        if (t + 1 >= NHIST && t + 1 < tcut) {
            const float* Ut = &g_U[(size_t)(t + 1) * 192];
            kn0 = Ut[j]; kn1 = Ut[64 + j]; kn2 = Ut[128 + j];
        }

        // ---- h-GEMV: broadcast reads, register weights, FFMA2 ----
        ull a0 = 0, a1 = 0, a2 = 0, a3 = 0;
        const ulonglong2* hp = (const ulonglong2*)sh[par];
        #pragma unroll
        for (int q = 0; q < 16; q++) {
            ulonglong2 hv = hp[q];               // h[4q..4q+3]
            if (q & 1) { fma2(a2, hv.x, whh[2 * q]); fma2(a3, hv.y, whh[2 * q + 1]); }
            else       { fma2(a0, hv.x, whh[2 * q]); fma2(a1, hv.y, whh[2 * q + 1]); }
        }
        float2 A0 = unpack2(a0), A1 = unpack2(a1), A2 = unpack2(a2), A3 = unpack2(a3);
        float pre = bj + xwc + (((A0.x + A0.y) + (A1.x + A1.y))
                              + ((A2.x + A2.y) + (A3.x + A3.y)));
        float ho = hcur * 0.8f + fmaxf(pre, 0.f) * 0.2f;

        // ---- Kalman correction (active only for NHIST <= t < tcut) ----
        if (t >= NHIST && t < tcut) {
            float p0 = -Cj0 * ho, p1 = -Cj1 * ho, p2 = -Cj2 * ho;
            #pragma unroll
            for (int sd = 0; sd < NHIST; sd++) {
                float hv = hist[sd];
                p0 += g_CW[0 * 320 + sd * 64 + j] * hv;
                p1 += g_CW[1 * 320 + sd * 64 + j] * hv;
                p2 += g_CW[2 * 320 + sd * 64 + j] * hv;
            }
            #pragma unroll
            for (int off = 16; off; off >>= 1) {
                p0 += __shfl_xor_sync(FULLM, p0, off);
                p1 += __shfl_xor_sync(FULLM, p1, off);
                p2 += __shfl_xor_sync(FULLM, p2, off);
            }
            if (lane == 0) {
                sred[w][0] = p0; sred[w][1] = p1; sred[w][2] = p2;
            }
            __syncthreads();
            p0 = sred[0][0] + sred[1][0] + cb0;
            p1 = sred[0][1] + sred[1][1] + cb1;
            p2 = sred[0][2] + sred[1][2] + cb2;
            ho += k0 * p0 + k1 * p1 + k2 * p2;
        }

        // ---- history shift (dead once the correction window closes) ----
        if (t + 1 < tcut) {
            #pragma unroll
            for (int sd = 0; sd < NHIST - 1; sd++) hist[sd] = hist[sd + 1];
            hist[NHIST - 1] = ho;
        }

        // ---- publish state, write output, advance pipeline ----
        sh[par ^ 1][j] = ho;
        *outp = ho;
        __syncthreads();

        hcur = ho;
        xwc = xw1; xw1 = xw2; xw2 = xw3;
        k0 = kn0; k1 = kn1; k2 = kn2;
        outp += XSTP;
        par ^= 1;
    }

    if (hlast) hlast[(size_t)row * HH + j] = hcur;
}

// ======================================================================
extern "C" void kernel_launch(void* const* d_in, const int* in_sizes, int n_in,
                              void* d_out, int out_size) {
    const float* x     = (const float*)d_in[0];
    const float* W_ih  = (const float*)d_in[1];
    const float* b_ih  = (const float*)d_in[2];
    const float* W_hh  = (const float*)d_in[3];
    const float* b_hh  = (const float*)d_in[4];
    const float* C     = (const float*)d_in[5];
    const float* W_mlp = (const float*)d_in[6];
    const float* b_mlp = (const float*)d_in[7];
    float* out = (float*)d_out;

    const long long main_elems = (long long)TT * BB * HH;
    float* hlast = ((long long)out_size >= main_elems + (long long)BB * HH)
                       ? out + main_elems : nullptr;

    cudaFuncSetAttribute(cov_kernel, cudaFuncAttributeMaxDynamicSharedMemorySize,
                         (int)sizeof(PSmem));

    cov_kernel<<<1, 256, sizeof(PSmem)>>>(W_hh, C, W_mlp, b_mlp);
    xw_kernel<<<(TT * BB) / 128, 256>>>(x, W_ih);
    seq_kernel<<<BB, 64>>>(b_ih, b_hh, W_hh, C, out, hlast);
}

// round 17
// speedup vs baseline: 1.4090x; 1.4090x over previous
#include <cuda_runtime.h>
#include <cstdint>

#define TT 1000
#define BB 512
#define IDM 32
#define HH 64
#define NHIST 5
#define FULLM 0xffffffffu

typedef unsigned long long ull;

// Kalman gains per step: layout [t][o*64 + i]
__device__ __align__(16) float g_U[TT * 192];
// first step with zero Kalman gain: correction active iff NHIST <= t < g_tcut
__device__ int g_tcut;
// CW = C @ W_mlp  (3 x 320), Cb = C @ b_mlp (3)
__device__ __align__(16) float g_CW[3 * 320];
__device__ __align__(16) float g_Cb[4];

// ---- packed f32x2 helpers (Blackwell FFMA2 path, PTX-only) ----
__device__ __forceinline__ void fma2(ull& d, ull a, ull b) {
    asm("fma.rn.f32x2 %0, %1, %2, %0;" : "+l"(d) : "l"(a), "l"(b));
}
__device__ __forceinline__ ull pack2(float lo, float hi) {
    ull r; asm("mov.b64 %0, {%1, %2};" : "=l"(r) : "f"(lo), "f"(hi)); return r;
}
__device__ __forceinline__ float2 unpack2(ull v) {
    float2 r; asm("mov.b64 {%0, %1}, %2;" : "=f"(r.x), "=f"(r.y) : "l"(v)); return r;
}

// ======================================================================
// Producer: prep (CW fold) + Riccati chain -> K_t. Single block,
// 256 threads, 4x4 tiles, f32x2 GEMMs (best measured config, 12us/iter).
// Exit when max|K| <= 1e-3 (calibrated: rel_err ~ 0.045*thr => ~4.5e-5).
// ======================================================================
#define PD 66

struct PSmem {
    float A[64 * PD];
    float At[64 * PD];
    float cov[64 * PD];
    float E[64 * PD];
    float P[64 * PD];
    float Cs[192];
    float Y[192];
    float S[9];
    float Si[9];
    float U[192];
    float Up[192];
    float CP[192];
    int ctl[2];
    int done;
};

__global__ void __launch_bounds__(256, 1)
cov_kernel(const float* __restrict__ W_hh, const float* __restrict__ Cmat,
           const float* __restrict__ W_mlp, const float* __restrict__ b_mlp) {
    extern __shared__ char praw[];
    PSmem& s = *reinterpret_cast<PSmem*>(praw);
    const int tid = threadIdx.x;

    for (int idx = tid; idx < 960; idx += 256) {
        int o = idx / 320, m = idx - o * 320;
        float acc = 0.f;
        #pragma unroll 8
        for (int j = 0; j < 64; j++) acc += Cmat[o * 64 + j] * W_mlp[j * 320 + m];
        g_CW[idx] = acc;
    }
    if (tid < 3) {
        float acc = 0.f;
        for (int j = 0; j < 64; j++) acc += Cmat[tid * 64 + j] * b_mlp[j];
        g_Cb[tid] = acc;
    }
    if (tid == 5) g_tcut = TT;

    for (int idx = tid; idx < 4096; idx += 256) {
        int i = idx >> 6, k = idx & 63;
        float v = W_hh[idx];
        s.A[i * PD + k]   = v;
        s.At[k * PD + i]  = v;
        s.cov[i * PD + k] = (i == k) ? 1.f : 0.f;
    }
    for (int idx = tid; idx < 192; idx += 256) { s.Cs[idx] = Cmat[idx]; s.Up[idx] = 0.f; }
    if (tid < 2) s.ctl[tid] = 0;
    if (tid == 0) s.done = 0;
    __syncthreads();

    const int ty = tid >> 4;
    const int tx = tid & 15;

    for (int t = NHIST; t < TT; t++) {
        {   // E = A @ cov
            ull c01[4] = {0, 0, 0, 0};
            ull c23[4] = {0, 0, 0, 0};
            #pragma unroll 4
            for (int k = 0; k < 64; k++) {
                ull b01 = *(const ull*)&s.cov[k * PD + tx * 4];
                ull b23 = *(const ull*)&s.cov[k * PD + tx * 4 + 2];
                #pragma unroll
                for (int r = 0; r < 4; r++) {
                    float av = s.A[(ty * 4 + r) * PD + k];
                    ull ap = pack2(av, av);
                    fma2(c01[r], ap, b01);
                    fma2(c23[r], ap, b23);
                }
            }
            #pragma unroll
            for (int r = 0; r < 4; r++) {
                *(float2*)&s.E[(ty * 4 + r) * PD + tx * 4]     = unpack2(c01[r]);
                *(float2*)&s.E[(ty * 4 + r) * PD + tx * 4 + 2] = unpack2(c23[r]);
            }
        }
        __syncthreads();

        {   // P = E @ A^T
            ull c01[4] = {0, 0, 0, 0};
            ull c23[4] = {0, 0, 0, 0};
            #pragma unroll 4
            for (int k = 0; k < 64; k++) {
                ull b01 = *(const ull*)&s.At[k * PD + tx * 4];
                ull b23 = *(const ull*)&s.At[k * PD + tx * 4 + 2];
                #pragma unroll
                for (int r = 0; r < 4; r++) {
                    float av = s.E[(ty * 4 + r) * PD + k];
                    ull ap = pack2(av, av);
                    fma2(c01[r], ap, b01);
                    fma2(c23[r], ap, b23);
                }
            }
            #pragma unroll
            for (int r = 0; r < 4; r++) {
                *(float2*)&s.P[(ty * 4 + r) * PD + tx * 4]     = unpack2(c01[r]);
                *(float2*)&s.P[(ty * 4 + r) * PD + tx * 4 + 2] = unpack2(c23[r]);
            }
        }
        __syncthreads();

        if (tid < 192) {   // Y = P @ C^T
            int o = tid >> 6, i = tid & 63;
            float acc = 0.f;
            for (int k = 0; k < 64; k++) acc += s.P[i * PD + k] * s.Cs[o * 64 + k];
            s.Y[i * 3 + o] = acc;
        }
        __syncthreads();

        if (tid < 9) {     // S = C @ Y + I
            int o1 = tid / 3, o2 = tid - o1 * 3;
            float acc = (o1 == o2) ? 1.f : 0.f;
            for (int k = 0; k < 64; k++) acc += s.Cs[o1 * 64 + k] * s.Y[k * 3 + o2];
            s.S[tid] = acc;
        }
        __syncthreads();

        if (tid == 0) {    // Si = inv(S)
            float a = s.S[0], b = s.S[1], c = s.S[2];
            float d = s.S[3], e = s.S[4], f = s.S[5];
            float g = s.S[6], h = s.S[7], i2 = s.S[8];
            float A0 =  (e * i2 - f * h);
            float A1 = -(d * i2 - f * g);
            float A2 =  (d * h  - e * g);
            float B0 = -(b * i2 - c * h);
            float B1 =  (a * i2 - c * g);
            float B2 = -(a * h  - b * g);
            float C0 =  (b * f - c * e);
            float C1 = -(a * f - c * d);
            float C2 =  (a * e - b * d);
            float det = a * A0 + b * A1 + c * A2;
            float id = 1.f / det;
            s.Si[0] = A0 * id; s.Si[1] = B0 * id; s.Si[2] = C0 * id;
            s.Si[3] = A1 * id; s.Si[4] = B1 * id; s.Si[5] = C1 * id;
            s.Si[6] = A2 * id; s.Si[7] = B2 * id; s.Si[8] = C2 * id;
        }
        __syncthreads();

        if (tid < 192) {   // U = Y @ Si (K), store, track
            int o = tid >> 6, i = tid & 63;
            float u = s.Y[i * 3 + 0] * s.Si[0 + o]
                    + s.Y[i * 3 + 1] * s.Si[3 + o]
                    + s.Y[i * 3 + 2] * s.Si[6 + o];
            s.U[tid] = u;
            g_U[(size_t)t * 192 + tid] = u;
            float dd = fabsf(u - s.Up[tid]);
            s.Up[tid] = u;
            atomicMax(&s.ctl[0], __float_as_int(dd));
            atomicMax(&s.ctl[1], __float_as_int(fabsf(u)));
        }
        __syncthreads();

        if (tid < 192) {   // CP = C @ P
            int o = tid >> 6, j = tid & 63;
            float acc = 0.f;
            for (int k = 0; k < 64; k++) acc += s.Cs[o * 64 + k] * s.P[k * PD + j];
            s.CP[tid] = acc;
        }
        if (tid == 0) {
            float md = __int_as_float(s.ctl[0]);
            float ma = __int_as_float(s.ctl[1]);
            if (ma <= 1e-3f)            s.done = 2;  // K negligible (calibrated)
            else if (md <= 1e-6f * ma)  s.done = 1;  // K stationary (nonzero)
            s.ctl[0] = 0; s.ctl[1] = 0;
        }
        __syncthreads();

        for (int e = tid; e < 4096; e += 256) {   // cov = P - U^T CP
            int i = e >> 6, j = e & 63;
            s.cov[i * PD + j] = s.P[i * PD + j]
                - (s.U[i]       * s.CP[j]
                 + s.U[64 + i]  * s.CP[64 + j]
                 + s.U[128 + i] * s.CP[128 + j]);
        }
        __syncthreads();

        if (s.done == 2) {
            if (tid == 0) g_tcut = t + 1;
            break;
        }
        if (s.done == 1) {
            for (int tt = t + 1; tt < TT; tt++)
                for (int idx = tid; idx < 192; idx += 256)
                    g_U[(size_t)tt * 192 + idx] = s.U[idx];
            break;
        }
    }
}

// ======================================================================
// Consumer: R14's measured shape (block = 64 threads = 1 row, lane owns
// dim j, register-stationary weights, one barrier/step), with the time
// loop SPLIT at tcut: lean tail body has no correction/history/K code.
// ======================================================================
__global__ void __launch_bounds__(64, 1)
seq_kernel(const float* __restrict__ x,
           const float* __restrict__ W_ih, const float* __restrict__ b_ih,
           const float* __restrict__ W_hh, const float* __restrict__ b_hh,
           const float* __restrict__ C,
           float* __restrict__ out, float* __restrict__ hlast) {
    __shared__ __align__(16) float sh[2][64];   // parity-buffered hidden
    __shared__ __align__(16) float sx[2][32];   // parity-buffered x
    __shared__ float sred[2][4];                // correction warp partials

    const int tid  = threadIdx.x;
    const int w    = tid >> 5;
    const int lane = tid & 31;
    const int j    = tid;          // output dim owned by this lane
    const int row  = blockIdx.x;

    // ---- weights into registers (f32x2-packed) ----
    ull whh[32], wih[16];
    #pragma unroll
    for (int p = 0; p < 32; p++)
        whh[p] = *(const ull*)&W_hh[j * HH + 2 * p];
    #pragma unroll
    for (int p = 0; p < 16; p++)
        wih[p] = *(const ull*)&W_ih[j * IDM + 2 * p];

    const float Cj0 = C[j], Cj1 = C[64 + j], Cj2 = C[128 + j];
    const float bj  = b_ih[j] + b_hh[j];
    const float cb0 = g_Cb[0], cb1 = g_Cb[1], cb2 = g_Cb[2];
    const int   tcut = g_tcut;     // correction active iff NHIST <= t < tcut

    // ---- init state ----
    sh[0][j] = 0.f;
    float hcur = 0.f;
    float hist[NHIST] = {0.f, 0.f, 0.f, 0.f, 0.f};
    float xn1 = 0.f, xn2 = 0.f;
    if (w == 0) {
        sx[0][lane] = x[(size_t)row * IDM + lane];
        xn1 = x[((size_t)1 * BB + row) * IDM + lane];
        xn2 = x[((size_t)2 * BB + row) * IDM + lane];
    }
    float k0 = 0.f, k1 = 0.f, k2 = 0.f;
    int par = 0;
    float* outp = out + (size_t)row * HH + j;
    const size_t OSTP = (size_t)BB * HH;
    __syncthreads();

    int t = 0;
    const int tstop = (tcut < TT) ? tcut : TT;

    // ================= head loop: full machinery (t < tcut) =============
    for (; t < tstop; t++) {
        float xn3 = 0.f;
        if (w == 0 && t + 3 < TT)
            xn3 = x[((size_t)(t + 3) * BB + row) * IDM + lane];
        float kn0 = 0.f, kn1 = 0.f, kn2 = 0.f;
        if (t + 1 >= NHIST && t + 1 < tcut) {
            const float* Ut = &g_U[(size_t)(t + 1) * 192];
            kn0 = Ut[j]; kn1 = Ut[64 + j]; kn2 = Ut[128 + j];
        }

        ull a0 = 0, a1 = 0, a2 = 0, a3 = 0;
        const ulonglong2* hp = (const ulonglong2*)sh[par];
        #pragma unroll
        for (int q = 0; q < 16; q++) {
            ulonglong2 hv = hp[q];
            if (q & 1) { fma2(a2, hv.x, whh[2 * q]); fma2(a3, hv.y, whh[2 * q + 1]); }
            else       { fma2(a0, hv.x, whh[2 * q]); fma2(a1, hv.y, whh[2 * q + 1]); }
        }
        const ulonglong2* xp = (const ulonglong2*)sx[par];
        #pragma unroll
        for (int q = 0; q < 8; q++) {
            ulonglong2 xv = xp[q];
            if (q & 1) { fma2(a2, xv.x, wih[2 * q]); fma2(a3, xv.y, wih[2 * q + 1]); }
            else       { fma2(a0, xv.x, wih[2 * q]); fma2(a1, xv.y, wih[2 * q + 1]); }
        }
        float2 A0 = unpack2(a0), A1 = unpack2(a1), A2 = unpack2(a2), A3 = unpack2(a3);
        float pre = bj + (((A0.x + A0.y) + (A1.x + A1.y))
                        + ((A2.x + A2.y) + (A3.x + A3.y)));
        float ho = hcur * 0.8f + fmaxf(pre, 0.f) * 0.2f;

        if (t >= NHIST) {
            float p0 = -Cj0 * ho, p1 = -Cj1 * ho, p2 = -Cj2 * ho;
            #pragma unroll
            for (int sd = 0; sd < NHIST; sd++) {
                float hv = hist[sd];
                p0 += g_CW[0 * 320 + sd * 64 + j] * hv;
                p1 += g_CW[1 * 320 + sd * 64 + j] * hv;
                p2 += g_CW[2 * 320 + sd * 64 + j] * hv;
            }
            #pragma unroll
            for (int off = 16; off; off >>= 1) {
                p0 += __shfl_xor_sync(FULLM, p0, off);
                p1 += __shfl_xor_sync(FULLM, p1, off);
                p2 += __shfl_xor_sync(FULLM, p2, off);
            }
            if (lane == 0) {
                sred[w][0] = p0; sred[w][1] = p1; sred[w][2] = p2;
            }
            __syncthreads();
            p0 = sred[0][0] + sred[1][0] + cb0;
            p1 = sred[0][1] + sred[1][1] + cb1;
            p2 = sred[0][2] + sred[1][2] + cb2;
            ho += k0 * p0 + k1 * p1 + k2 * p2;
        }

        #pragma unroll
        for (int sd = 0; sd < NHIST - 1; sd++) hist[sd] = hist[sd + 1];
        hist[NHIST - 1] = ho;

        sh[par ^ 1][j] = ho;
        if (w == 0) sx[par ^ 1][lane] = xn1;
        *outp = ho;
        __syncthreads();

        hcur = ho;
        xn1 = xn2; xn2 = xn3;
        k0 = kn0; k1 = kn1; k2 = kn2;
        outp += OSTP;
        par ^= 1;
    }

    // ================= lean tail: no correction machinery ===============
    for (; t < TT; t++) {
        float xn3 = 0.f;
        if (w == 0 && t + 3 < TT)
            xn3 = x[((size_t)(t + 3) * BB + row) * IDM + lane];

        ull a0 = 0, a1 = 0, a2 = 0, a3 = 0;
        const ulonglong2* hp = (const ulonglong2*)sh[par];
        #pragma unroll
        for (int q = 0; q < 16; q++) {
            ulonglong2 hv = hp[q];
            if (q & 1) { fma2(a2, hv.x, whh[2 * q]); fma2(a3, hv.y, whh[2 * q + 1]); }
            else       { fma2(a0, hv.x, whh[2 * q]); fma2(a1, hv.y, whh[2 * q + 1]); }
        }
        const ulonglong2* xp = (const ulonglong2*)sx[par];
        #pragma unroll
        for (int q = 0; q < 8; q++) {
            ulonglong2 xv = xp[q];
            if (q & 1) { fma2(a2, xv.x, wih[2 * q]); fma2(a3, xv.y, wih[2 * q + 1]); }
            else       { fma2(a0, xv.x, wih[2 * q]); fma2(a1, xv.y, wih[2 * q + 1]); }
        }
        float2 A0 = unpack2(a0), A1 = unpack2(a1), A2 = unpack2(a2), A3 = unpack2(a3);
        float pre = bj + (((A0.x + A0.y) + (A1.x + A1.y))
                        + ((A2.x + A2.y) + (A3.x + A3.y)));
        float ho = hcur * 0.8f + fmaxf(pre, 0.f) * 0.2f;

        sh[par ^ 1][j] = ho;
        if (w == 0) sx[par ^ 1][lane] = xn1;
        *outp = ho;
        __syncthreads();

        hcur = ho;
        xn1 = xn2; xn2 = xn3;
        outp += OSTP;
        par ^= 1;
    }

    if (hlast) hlast[(size_t)row * HH + j] = hcur;
}

// ======================================================================
extern "C" void kernel_launch(void* const* d_in, const int* in_sizes, int n_in,
                              void* d_out, int out_size) {
    const float* x     = (const float*)d_in[0];
    const float* W_ih  = (const float*)d_in[1];
    const float* b_ih  = (const float*)d_in[2];
    const float* W_hh  = (const float*)d_in[3];
    const float* b_hh  = (const float*)d_in[4];
    const float* C     = (const float*)d_in[5];
    const float* W_mlp = (const float*)d_in[6];
    const float* b_mlp = (const float*)d_in[7];
    float* out = (float*)d_out;

    const long long main_elems = (long long)TT * BB * HH;
    float* hlast = ((long long)out_size >= main_elems + (long long)BB * HH)
                       ? out + main_elems : nullptr;

    cudaFuncSetAttribute(cov_kernel, cudaFuncAttributeMaxDynamicSharedMemorySize,
                         (int)sizeof(PSmem));

    cov_kernel<<<1, 256, sizeof(PSmem)>>>(W_hh, C, W_mlp, b_mlp);
    seq_kernel<<<BB, 64>>>(x, W_ih, b_ih, W_hh, b_hh, C, out, hlast);
}